// round 1
// baseline (speedup 1.0000x reference)
#include <cuda_runtime.h>
#include <cuda_bf16.h>
#include <math.h>

#define N_TOKENS 16384
#define D_MODEL  512
#define NQ       10
#define NL       2
#define DIM      1024   // 2^NQ

// ---------------- scratch (device globals; no allocations allowed) ----------
__device__ __align__(16) float g_Ur[DIM * DIM];
__device__ __align__(16) float g_Ui[DIM * DIM];
__device__ __align__(16) float g_xq[N_TOKENS * DIM];   // xq, then psi (in-place normalize)
__device__ __align__(16) float g_re[N_TOKENS * DIM];   // re, then probs (in-place)
__device__ __align__(16) float g_im[N_TOKENS * DIM];
__device__ __align__(16) float g_out[N_TOKENS * D_MODEL];

// ---------------- complex helpers -------------------------------------------
__device__ __forceinline__ float2 cmul(float2 a, float2 b) {
    return make_float2(a.x * b.x - a.y * b.y, a.x * b.y + a.y * b.x);
}
__device__ __forceinline__ float2 cadd(float2 a, float2 b) {
    return make_float2(a.x + b.x, a.y + b.y);
}

// ---------------- kernel 1: build circuit unitary ---------------------------
// Block j simulates basis state e_j through the circuit -> column U[:, j].
// State (1024 complex) lives in shared memory; 60 rotations folded into 20
// combined 2x2 complex gates (Rz*Ry*Rx per qubit per layer) + CZ phase passes.
__global__ void build_unitary(const float* __restrict__ rot,
                              const float* __restrict__ ent,
                              float* __restrict__ Ur, float* __restrict__ Ui) {
    __shared__ float2 st[DIM];
    const int j = blockIdx.x;
    const int t = threadIdx.x;   // 256 threads

    for (int i = t; i < DIM; i += 256)
        st[i] = make_float2(i == j ? 1.f : 0.f, 0.f);
    __syncthreads();

    for (int l = 0; l < NL; l++) {
        for (int q = 0; q < NQ; q++) {
            const float t1 = rot[(l * NQ + q) * 3 + 0];
            const float t2 = rot[(l * NQ + q) * 3 + 1];
            const float t3 = rot[(l * NQ + q) * 3 + 2];
            // Rx
            float c1, s1; sincosf(0.5f * t1, &s1, &c1);
            float2 rx00 = {c1, 0.f}, rx01 = {0.f, -s1}, rx10 = {0.f, -s1}, rx11 = {c1, 0.f};
            // Ry
            float c2, s2; sincosf(0.5f * t2, &s2, &c2);
            float2 ry00 = {c2, 0.f}, ry01 = {-s2, 0.f}, ry10 = {s2, 0.f}, ry11 = {c2, 0.f};
            // A = Ry * Rx
            float2 a00 = cadd(cmul(ry00, rx00), cmul(ry01, rx10));
            float2 a01 = cadd(cmul(ry00, rx01), cmul(ry01, rx11));
            float2 a10 = cadd(cmul(ry10, rx00), cmul(ry11, rx10));
            float2 a11 = cadd(cmul(ry10, rx01), cmul(ry11, rx11));
            // M = Rz * A   (Rz = diag(e^{-i t3/2}, e^{+i t3/2}))
            float cz, sz; sincosf(0.5f * t3, &sz, &cz);
            float2 ez0 = {cz, -sz}, ez1 = {cz, sz};
            float2 m00 = cmul(ez0, a00), m01 = cmul(ez0, a01);
            float2 m10 = cmul(ez1, a10), m11 = cmul(ez1, a11);

            const int mask = 1 << (NQ - 1 - q);
            for (int p = t; p < DIM / 2; p += 256) {
                int i0 = ((p & ~(mask - 1)) << 1) | (p & (mask - 1));
                int i1 = i0 | mask;
                float2 v0 = st[i0], v1 = st[i1];
                st[i0] = cadd(cmul(m00, v0), cmul(m01, v1));
                st[i1] = cadd(cmul(m10, v0), cmul(m11, v1));
            }
            __syncthreads();
        }
        // parameterized CZ chain: combine all 9 phases in one pass
        for (int i = t; i < DIM; i += 256) {
            float ang = 0.f;
            #pragma unroll
            for (int g = 0; g < NQ - 1; g++) {
                int b1 = (i >> (NQ - 1 - g)) & 1;
                int b2 = (i >> (NQ - 2 - g)) & 1;
                if (b1 & b2) ang += ent[l * (NQ - 1) + g];
            }
            float sn, cs; sincosf(ang, &sn, &cs);
            st[i] = cmul(st[i], make_float2(cs, sn));
        }
        __syncthreads();
    }

    for (int i = t; i < DIM; i += 256) {
        Ur[i * DIM + j] = st[i].x;
        Ui[i * DIM + j] = st[i].y;
    }
}

// ---------------- kernel 2: fp32 SGEMM (NT): C[m,n] = sum_k A[m,k]*B[n,k] ---
// 128x128 tile, BK=8, 256 threads, 8x8 per thread. M,N,K multiples of 128/8.
__global__ __launch_bounds__(256, 2)
void sgemm_nt(const float* __restrict__ A, const float* __restrict__ B,
              float* __restrict__ C, int M, int N, int K,
              const float* __restrict__ bias) {
    __shared__ float As[8][128];
    __shared__ float Bs[8][128];

    const int tid = threadIdx.x;
    const int tx = tid & 15;          // 16 cols of threads
    const int ty = tid >> 4;          // 16 rows of threads
    const int bm = blockIdx.y * 128;
    const int bn = blockIdx.x * 128;

    const int lr = tid >> 1;          // 0..127: row within tile for loading
    const int lk = (tid & 1) * 4;     // 0 or 4: K offset for float4 load

    const float* Aptr = A + (size_t)(bm + lr) * K + lk;
    const float* Bptr = B + (size_t)(bn + lr) * K + lk;

    float acc[8][8];
    #pragma unroll
    for (int i = 0; i < 8; i++)
        #pragma unroll
        for (int jj = 0; jj < 8; jj++) acc[i][jj] = 0.f;

    for (int k0 = 0; k0 < K; k0 += 8) {
        float4 av = *(const float4*)(Aptr + k0);
        float4 bv = *(const float4*)(Bptr + k0);
        __syncthreads();
        As[lk + 0][lr] = av.x; As[lk + 1][lr] = av.y;
        As[lk + 2][lr] = av.z; As[lk + 3][lr] = av.w;
        Bs[lk + 0][lr] = bv.x; Bs[lk + 1][lr] = bv.y;
        Bs[lk + 2][lr] = bv.z; Bs[lk + 3][lr] = bv.w;
        __syncthreads();

        #pragma unroll
        for (int k = 0; k < 8; k++) {
            float a[8], b[8];
            *(float4*)(a)     = *(const float4*)&As[k][ty * 8];
            *(float4*)(a + 4) = *(const float4*)&As[k][ty * 8 + 4];
            *(float4*)(b)     = *(const float4*)&Bs[k][tx * 8];
            *(float4*)(b + 4) = *(const float4*)&Bs[k][tx * 8 + 4];
            #pragma unroll
            for (int i = 0; i < 8; i++)
                #pragma unroll
                for (int jj = 0; jj < 8; jj++)
                    acc[i][jj] = fmaf(a[i], b[jj], acc[i][jj]);
        }
    }

    #pragma unroll
    for (int i = 0; i < 8; i++) {
        int m = bm + ty * 8 + i;
        #pragma unroll
        for (int jj = 0; jj < 8; jj++) {
            int n = bn + tx * 8 + jj;
            float v = acc[i][jj];
            if (bias) v += bias[n];
            C[(size_t)m * N + n] = v;
        }
    }
}

// ---------------- block reduce ----------------------------------------------
__device__ float blockReduceSum256(float v) {
    __shared__ float sh[8];
    __syncthreads();   // protect sh reuse across consecutive calls
    int lane = threadIdx.x & 31, wid = threadIdx.x >> 5;
    #pragma unroll
    for (int o = 16; o > 0; o >>= 1) v += __shfl_down_sync(0xffffffffu, v, o);
    if (lane == 0) sh[wid] = v;
    __syncthreads();
    float s = 0.f;
    if (threadIdx.x < 8) s = sh[threadIdx.x];
    if (wid == 0) {
        #pragma unroll
        for (int o = 4; o > 0; o >>= 1) s += __shfl_down_sync(0xffu, s, o);
        if (lane == 0) sh[0] = s;
    }
    __syncthreads();
    return sh[0];
}

// ---------------- kernel 3: row L2-normalize (in place, width 1024) ---------
__global__ void rownorm(float* __restrict__ xq) {
    const int row = blockIdx.x;
    float* p = xq + (size_t)row * DIM;
    const int t = threadIdx.x;
    float v0 = p[t], v1 = p[t + 256], v2 = p[t + 512], v3 = p[t + 768];
    float ss = blockReduceSum256(v0 * v0 + v1 * v1 + v2 * v2 + v3 * v3);
    float scale = 1.f / fmaxf(sqrtf(ss), 1e-12f);
    p[t] = v0 * scale; p[t + 256] = v1 * scale;
    p[t + 512] = v2 * scale; p[t + 768] = v3 * scale;
}

// ---------------- kernel 4: probs = re^2 + im^2 (in place into re) ----------
__global__ void probs_kernel(float* __restrict__ re, const float* __restrict__ im) {
    const size_t n = (size_t)N_TOKENS * DIM / 4;
    size_t i = blockIdx.x * (size_t)blockDim.x + threadIdx.x;
    size_t stride = (size_t)gridDim.x * blockDim.x;
    float4* r4 = (float4*)re;
    const float4* i4 = (const float4*)im;
    for (; i < n; i += stride) {
        float4 r = r4[i], m = i4[i];
        r.x = r.x * r.x + m.x * m.x;
        r.y = r.y * r.y + m.y * m.y;
        r.z = r.z * r.z + m.z * m.z;
        r.w = r.w * r.w + m.w * m.w;
        r4[i] = r;
    }
}

// ---------------- kernel 5: LayerNorm(512) -> d_out --------------------------
__global__ void layernorm(const float* __restrict__ in,
                          const float* __restrict__ w, const float* __restrict__ b,
                          float* __restrict__ out) {
    const int row = blockIdx.x;
    const float* p = in + (size_t)row * D_MODEL;
    const int t = threadIdx.x;
    float v0 = p[t], v1 = p[t + 256];
    float mu = blockReduceSum256(v0 + v1) * (1.f / D_MODEL);
    float d0 = v0 - mu, d1 = v1 - mu;
    float var = blockReduceSum256(d0 * d0 + d1 * d1) * (1.f / D_MODEL);
    float inv = rsqrtf(var + 1e-5f);
    float* o = out + (size_t)row * D_MODEL;
    o[t]       = d0 * inv * w[t]       + b[t];
    o[t + 256] = d1 * inv * w[t + 256] + b[t + 256];
}

// ---------------- launch ------------------------------------------------------
extern "C" void kernel_launch(void* const* d_in, const int* in_sizes, int n_in,
                              void* d_out, int out_size) {
    const float* x     = (const float*)d_in[0];
    const float* W_in  = (const float*)d_in[1];
    const float* b_in  = (const float*)d_in[2];
    const float* W_out = (const float*)d_in[3];
    const float* b_out = (const float*)d_in[4];
    const float* rot   = (const float*)d_in[5];
    const float* ent   = (const float*)d_in[6];
    const float* ln_w  = (const float*)d_in[7];
    const float* ln_b  = (const float*)d_in[8];
    float* out = (float*)d_out;

    float *Ur, *Ui, *xq, *re, *im, *pre;
    cudaGetSymbolAddress((void**)&Ur,  g_Ur);
    cudaGetSymbolAddress((void**)&Ui,  g_Ui);
    cudaGetSymbolAddress((void**)&xq,  g_xq);
    cudaGetSymbolAddress((void**)&re,  g_re);
    cudaGetSymbolAddress((void**)&im,  g_im);
    cudaGetSymbolAddress((void**)&pre, g_out);

    // 1) circuit unitary (1024 x 1024 complex, split into Ur/Ui)
    build_unitary<<<DIM, 256>>>(rot, ent, Ur, Ui);

    // 2) xq = x @ W_in^T + b_in
    sgemm_nt<<<dim3(DIM / 128, N_TOKENS / 128), 256>>>(x, W_in, xq,
                                                       N_TOKENS, DIM, D_MODEL, b_in);
    // 3) psi = normalize(xq) (in place)
    rownorm<<<N_TOKENS, 256>>>(xq);

    // 4) re = psi @ Ur^T ; im = psi @ Ui^T
    sgemm_nt<<<dim3(DIM / 128, N_TOKENS / 128), 256>>>(xq, Ur, re,
                                                       N_TOKENS, DIM, DIM, nullptr);
    sgemm_nt<<<dim3(DIM / 128, N_TOKENS / 128), 256>>>(xq, Ui, im,
                                                       N_TOKENS, DIM, DIM, nullptr);
    // 5) probs = re^2 + im^2 (into re)
    probs_kernel<<<4096, 256>>>(re, im);

    // 6) pre = probs @ W_out^T + b_out
    sgemm_nt<<<dim3(D_MODEL / 128, N_TOKENS / 128), 256>>>(re, W_out, pre,
                                                           N_TOKENS, D_MODEL, DIM, b_out);
    // 7) LayerNorm -> d_out
    layernorm<<<N_TOKENS, 256>>>(pre, ln_w, ln_b, out);
}